// round 17
// baseline (speedup 1.0000x reference)
#include <cuda_runtime.h>
#include <cuda_fp16.h>
#include <cstdint>

// ============================================================
// Problem constants
// ============================================================
#define M_TOTAL   65536          // B*NP = 16*4096
#define K_DIM     768
#define N_DIM     1152
#define POS_SIZE  64

// Tiling (R10/R15-proven): CTA 128x128, 4 warps (2m x 2n), warp tile 64x64
#define M_TILE    128
#define N_TILE    128
#define K_CHUNK   64                       // fp16 elems per pipeline chunk
#define NUM_CHUNKS (K_DIM / K_DIM * 12)    // 12
#define NTILES_X  (N_DIM / N_TILE)         // 9
#define NTILES    ((M_TOTAL / M_TILE) * NTILES_X)   // 4608
#define GRID_P    444                      // 148 SMs x 3 CTAs (persistent)

// SMEM rows: 128B data + 16B pad = 144B (R10-proven conflict-free:
// 16r mod 128 distinct for r=0..7).
#define ROW_BYTES   144
#define TILE_BYTES  (128 * ROW_BYTES)      // 18432
#define STAGE_BYTES (2 * TILE_BYTES)       // 36864 (A then B)
#define SMEM_TOTAL  (2 * STAGE_BYTES)      // 73728 (3 CTAs = 221184B <= 228KB)

// ============================================================
// Scratch (device globals -- no allocation)
// ============================================================
__device__ __align__(256) __half g_A[(size_t)M_TOTAL * K_DIM];   // 96 MB
__device__ __align__(256) __half g_B[(size_t)N_DIM * K_DIM];     // 1.7 MB
__device__ int g_pos_is_i32;    // 1 if position ids are int32, 0 if int64
__device__ int g_pad_is_i32;    // 1 if padding mask is int32, 0 if 1-byte bool

// ============================================================
// Helpers
// ============================================================
__device__ __forceinline__ uint32_t smem_u32(const void* p) {
    uint32_t a;
    asm("{ .reg .u64 t; cvta.to.shared.u64 t, %1; cvt.u32.u64 %0, t; }"
        : "=r"(a) : "l"(p));
    return a;
}

#define CP_ASYNC16(saddr, gptr) \
    asm volatile("cp.async.cg.shared.global [%0], [%1], 16;" \
                 :: "r"(saddr), "l"(gptr) : "memory")
#define CP_COMMIT() asm volatile("cp.async.commit_group;" ::: "memory")
#define CP_WAIT0()  asm volatile("cp.async.wait_group 0;" ::: "memory")

#define LDMX4(R, addr) \
    asm volatile("ldmatrix.sync.aligned.m8n8.x4.shared.b16 {%0,%1,%2,%3}, [%4];" \
        : "=r"((R)[0]), "=r"((R)[1]), "=r"((R)[2]), "=r"((R)[3]) : "r"(addr))

// mma.sync m16n8k16 row.col f32.f16.f16.f32 (verified fragment layouts)
#define MMA16816(C, A, B) \
    asm volatile("mma.sync.aligned.m16n8k16.row.col.f32.f16.f16.f32 " \
        "{%0,%1,%2,%3}, {%4,%5,%6,%7}, {%8,%9}, {%0,%1,%2,%3};" \
        : "+f"((C)[0]), "+f"((C)[1]), "+f"((C)[2]), "+f"((C)[3]) \
        : "r"((A)[0]), "r"((A)[1]), "r"((A)[2]), "r"((A)[3]), \
          "r"((B)[0]), "r"((B)[1]))

// ============================================================
// Fused prep (vectorized): fp32->fp16 for A and B + dtype detectors.
//   Each convert thread: 32B in (2 x float4) -> 16B out (uint4).
// ============================================================
#define N8A (M_TOTAL * K_DIM / 8)          // 6,291,456
#define N8B (N_DIM * K_DIM / 8)            // 110,592
#define NBLK_A (N8A / 256)                 // 24576
#define NBLK_B (N8B / 256)                 // 432

__device__ __forceinline__ uint4 cvt8(float4 v0, float4 v1) {
    __half2 h0 = __floats2half2_rn(v0.x, v0.y);
    __half2 h1 = __floats2half2_rn(v0.z, v0.w);
    __half2 h2 = __floats2half2_rn(v1.x, v1.y);
    __half2 h3 = __floats2half2_rn(v1.z, v1.w);
    uint4 o;
    o.x = *reinterpret_cast<uint32_t*>(&h0);
    o.y = *reinterpret_cast<uint32_t*>(&h1);
    o.z = *reinterpret_cast<uint32_t*>(&h2);
    o.w = *reinterpret_cast<uint32_t*>(&h3);
    return o;
}

__global__ void prep_kernel(const float4* __restrict__ px,
                            const float4* __restrict__ W,
                            const int* __restrict__ pos,
                            const int* __restrict__ padw) {
    const int bid = blockIdx.x;
    if (bid < NBLK_A) {
        const int i = bid * 256 + threadIdx.x;
        reinterpret_cast<uint4*>(g_A)[i] = cvt8(px[2 * i], px[2 * i + 1]);
        return;
    }
    if (bid < NBLK_A + NBLK_B) {
        const int i = (bid - NBLK_A) * 256 + threadIdx.x;
        reinterpret_cast<uint4*>(g_B)[i] = cvt8(W[2 * i], W[2 * i + 1]);
        return;
    }
    // Detectors (verified R6-R15).
    __shared__ int sh[256];
    int acc = 0;
    const int which = bid - (NBLK_A + NBLK_B);
    if (which == 0) {
        for (int t = threadIdx.x; t < 2048; t += 256)
            acc |= pos[2 * t + 1];
    } else {
        for (int t = threadIdx.x; t < 16384; t += 256)
            acc |= (padw[t] & ~1);     // any bit beyond bit0 -> byte layout
    }
    sh[threadIdx.x] = acc;
    __syncthreads();
    for (int s = 128; s > 0; s >>= 1) {
        if (threadIdx.x < s) sh[threadIdx.x] |= sh[threadIdx.x + s];
        __syncthreads();
    }
    if (threadIdx.x == 0) {
        if (which == 0) g_pos_is_i32 = (sh[0] != 0) ? 1 : 0;
        else            g_pad_is_i32 = (sh[0] != 0) ? 0 : 1;
    }
}

// ============================================================
// Persistent GEMM + positional-embedding epilogue
//   grid = 444 CTAs, block = 128 (4 warps), 3 CTAs/SM.
//   Each CTA loops tiles t += 444 with a cross-tile cp.async pipeline:
//   last chunk of tile t issues chunk 0 of tile t+444; the epilogue
//   runs while it flies, hiding prologue+epilogue latency.
// ============================================================
__global__ void __launch_bounds__(128, 3) gemm_kernel(
    const void* __restrict__ pos_raw,           // [M_TOTAL, 2] i32 or i64
    const void* __restrict__ pad_raw,           // [M_TOTAL] i32 or u8
    const float* __restrict__ table,            // [2, 64, 1152] f32
    float* __restrict__ out)                    // [M_TOTAL, 1152] f32
{
    extern __shared__ char smem[];
    const uint32_t sbase = smem_u32(smem);
    const int tid  = threadIdx.x;
    const int lane = tid & 31;
    const int wid  = tid >> 5;
    const int wm   = wid & 1;          // 0..1  -> rows 64*wm
    const int wn   = wid >> 1;         // 0..1  -> cols 64*wn

    // Per-thread cp.async decomposition (row/seg fixed per thread across
    // the 8 units): unit u = tid + 128*k -> row = u>>3, seg = u&7.
    auto load_chunk = [&](const __half* gA, const __half* gB, int c, int stage) {
        const uint32_t s = sbase + (uint32_t)stage * STAGE_BYTES;
        const int kb = c * K_CHUNK;
#pragma unroll
        for (int k = 0; k < 8; k++) {
            const int u = tid + 128 * k;
            const int row = u >> 3, sg = u & 7;
            uint32_t sa = s + (uint32_t)(row * ROW_BYTES + sg * 16);
            CP_ASYNC16(sa, gA + (size_t)row * K_DIM + kb + sg * 8);
            CP_ASYNC16(sa + TILE_BYTES, gB + (size_t)row * K_DIM + kb + sg * 8);
        }
        CP_COMMIT();
    };

    // ldmatrix lane addresses (verified R7-R15), ROW_BYTES=144.
    const uint32_t a_lane = (uint32_t)((lane & 15) * ROW_BYTES + (lane >> 4) * 16);
    const uint32_t b_lane = (uint32_t)(((lane & 7) + ((lane >> 4) << 3)) * ROW_BYTES
                                       + (((lane >> 3) & 1) << 4));

    const int r4 = lane >> 2;
    const int qc = (lane & 3) * 2;
    const int pos_i32 = g_pos_is_i32;
    const int pad_i32 = g_pad_is_i32;
    const int* p32 = (const int*)pos_raw;
    const long long* p64 = (const long long*)pos_raw;
    const int* pd32 = (const int*)pad_raw;
    const unsigned char* pd8 = (const unsigned char*)pad_raw;

    int sp = 0;   // current stage parity (12 chunks/tile keeps continuity)

    // Prologue: first tile's chunk 0.
    {
        const int t0 = blockIdx.x;
        const __half* gA0 = g_A + (size_t)(t0 / NTILES_X) * M_TILE * K_DIM;
        const __half* gB0 = g_B + (size_t)(t0 % NTILES_X) * N_TILE * K_DIM;
        load_chunk(gA0, gB0, 0, 0);
    }

    for (int t = blockIdx.x; t < NTILES; t += GRID_P) {
        const int m_base = (t / NTILES_X) * M_TILE;
        const int n_base = (t % NTILES_X) * N_TILE;
        const __half* gA = g_A + (size_t)m_base * K_DIM;
        const __half* gB = g_B + (size_t)n_base * K_DIM;

        float acc[4][8][4];
#pragma unroll
        for (int i = 0; i < 4; i++)
#pragma unroll
            for (int j = 0; j < 8; j++)
#pragma unroll
                for (int e = 0; e < 4; e++) acc[i][j][e] = 0.0f;

#pragma unroll 1
        for (int c = 0; c < 12; c++) {
            CP_WAIT0();          // current chunk resident (only group pending)
            __syncthreads();     // visibility + all warps done with prev buffer

            // Refill the freed buffer: next chunk, or next tile's chunk 0.
            if (c + 1 < 12) {
                load_chunk(gA, gB, c + 1, sp ^ 1);
            } else if (t + GRID_P < NTILES) {
                const int tn = t + GRID_P;
                const __half* gAn = g_A + (size_t)(tn / NTILES_X) * M_TILE * K_DIM;
                const __half* gBn = g_B + (size_t)(tn % NTILES_X) * N_TILE * K_DIM;
                load_chunk(gAn, gBn, 0, sp ^ 1);
            }

            const uint32_t stg = sbase + (uint32_t)sp * STAGE_BYTES;
            const uint32_t As = stg + (uint32_t)(wm * 64 * ROW_BYTES) + a_lane;
            const uint32_t Bs = stg + TILE_BYTES
                              + (uint32_t)(wn * 64 * ROW_BYTES) + b_lane;

#pragma unroll
            for (int ks = 0; ks < 4; ks++) {
                uint32_t bf[8][2];
#pragma unroll
                for (int jj = 0; jj < 4; jj++) {
                    uint32_t t4[4];
                    LDMX4(t4, Bs + jj * 16 * ROW_BYTES + ks * 32);
                    bf[2 * jj][0]     = t4[0];
                    bf[2 * jj][1]     = t4[1];
                    bf[2 * jj + 1][0] = t4[2];
                    bf[2 * jj + 1][1] = t4[3];
                }
#pragma unroll
                for (int i = 0; i < 4; i++) {
                    uint32_t af[4];
                    LDMX4(af, As + i * 16 * ROW_BYTES + ks * 32);
#pragma unroll
                    for (int j = 0; j < 8; j++)
                        MMA16816(acc[i][j], af, bf[j]);
                }
            }
            sp ^= 1;
        }

        // ---- Epilogue (verified R6-R15) — runs while next tile's chunk 0
        //      cp.async is in flight; no smem use, no hazard. ----
#pragma unroll
        for (int i = 0; i < 4; i++) {
#pragma unroll
            for (int rh = 0; rh < 2; rh++) {
                const int m = m_base + wm * 64 + i * 16 + rh * 8 + r4;
                int xr, yr;
                if (pos_i32) {
                    xr = p32[(size_t)m * 2 + 0];
                    yr = p32[(size_t)m * 2 + 1];
                } else {
                    long long pxv = p64[(size_t)m * 2 + 0];
                    long long pyv = p64[(size_t)m * 2 + 1];
                    xr = (pxv < 0) ? 0 : (pxv > 63 ? 63 : (int)pxv);
                    yr = (pyv < 0) ? 0 : (pyv > 63 ? 63 : (int)pyv);
                }
                const int xi = (xr < 0) ? 0 : (xr > 63 ? 63 : xr);
                const int yi = (yr < 0) ? 0 : (yr > 63 ? 63 : yr);
                const bool pd = pad_i32 ? (pd32[m] != 0) : (pd8[m] != 0);
                const float* t0p = table + (size_t)xi * N_DIM;
                const float* t1p = table + (size_t)(POS_SIZE + yi) * N_DIM;
                float* orow = out + (size_t)m * N_DIM;
#pragma unroll
                for (int j = 0; j < 8; j++) {
                    const int n = n_base + wn * 64 + j * 8 + qc;
                    float v0 = acc[i][j][rh * 2 + 0];
                    float v1 = acc[i][j][rh * 2 + 1];
                    if (!pd) {
                        const float2 a = *reinterpret_cast<const float2*>(t0p + n);
                        const float2 b = *reinterpret_cast<const float2*>(t1p + n);
                        v0 += a.x + b.x;
                        v1 += a.y + b.y;
                    }
                    float2 o; o.x = v0; o.y = v1;
                    *reinterpret_cast<float2*>(orow + n) = o;
                }
            }
        }
    }
}

// ============================================================
// Launch — inputs identified by element count (all distinct):
//   pixel_values 50331648, pos 131072, pad 65536, W 884736, table 147456
// ============================================================
extern "C" void kernel_launch(void* const* d_in, const int* in_sizes, int n_in,
                              void* d_out, int out_size) {
    const float* px = nullptr;
    const void*  pos = nullptr;
    const void*  pad = nullptr;
    const float* W = nullptr;
    const float* table = nullptr;

    for (int i = 0; i < n_in; i++) {
        switch (in_sizes[i]) {
            case 50331648: px    = (const float*)d_in[i]; break;
            case 131072:   pos   = d_in[i];               break;
            case 65536:    pad   = d_in[i];               break;
            case 884736:   W     = (const float*)d_in[i]; break;
            case 147456:   table = (const float*)d_in[i]; break;
            default: break;
        }
    }
    if (!px)    px    = (const float*)d_in[0];
    if (!pos)   pos   = d_in[1];
    if (!pad)   pad   = d_in[2];
    if (!W)     W     = (const float*)d_in[3];
    if (!table) table = (const float*)d_in[4];

    float* out = (float*)d_out;

    prep_kernel<<<NBLK_A + NBLK_B + 2, 256>>>(
        (const float4*)px, (const float4*)W, (const int*)pos, (const int*)pad);

    cudaFuncSetAttribute(gemm_kernel, cudaFuncAttributeMaxDynamicSharedMemorySize,
                         SMEM_TOTAL);
    gemm_kernel<<<GRID_P, 128, SMEM_TOTAL>>>(pos, pad, table, out);
}